// round 16
// baseline (speedup 1.0000x reference)
#include <cuda_runtime.h>
#include <cuda_fp16.h>
#include <cstdint>
#include <math.h>

// Problem constants
constexpr int NB  = 8;     // batch
constexpr int NC  = 128;   // channels
constexpr int NP  = 2048;  // points
constexpr int NH  = 4;     // heads
constexpr int NCH = 512;   // c*h
constexpr int NZ  = NB * NH;  // 32 (b,h) slices
constexpr int NQK = 1024;  // q|k packed output width

// ---------------- scratch (static device globals; no allocation) -------------
__device__ __align__(1024) float  g_scale[NC];
__device__ __align__(1024) float  g_shift[NC];
__device__ __align__(1024) __half g_xh  [NB * NP * NC];        // x half [b][p][c]
__device__ __align__(1024) __half g_wqkv[1536 * 128];          // [(q|k|v)(h,c')][c]
__device__ __align__(1024) __half g_wo  [128 * 512];           // [c][(h,c')]
__device__ __align__(1024) float  g_bqkv[1536];
__device__ __align__(1024) __half g_qkh [NB * NP * NQK];       // [b][p][q|k (h,c')]
__device__ __align__(1024) __half g_vh  [NB * NCH * NP];       // [b][(h,c')][p]
__device__ __align__(1024) __half g_ath [NB * NP * NCH];       // [b][p][(h,c')]

// =================== PTX helpers =============================================
__device__ __forceinline__ uint32_t smem_u32(const void* p) {
    uint32_t a;
    asm("{ .reg .u64 t; cvta.to.shared.u64 t, %1; cvt.u32.u64 %0, t; }" : "=r"(a) : "l"(p));
    return a;
}
__device__ __forceinline__ void cp16(uint32_t s, const void* g) {
    asm volatile("cp.async.cg.shared.global [%0], [%1], 16;" :: "r"(s), "l"(g));
}
__device__ __forceinline__ void cp_commit() { asm volatile("cp.async.commit_group;"); }
__device__ __forceinline__ void cp_wait0()  { asm volatile("cp.async.wait_group 0;"); }
__device__ __forceinline__ void cp_wait1()  { asm volatile("cp.async.wait_group 1;"); }
__device__ __forceinline__ void ldsm4(uint32_t* r, uint32_t addr) {
    asm volatile("ldmatrix.sync.aligned.m8n8.x4.shared.b16 {%0,%1,%2,%3}, [%4];"
                 : "=r"(r[0]), "=r"(r[1]), "=r"(r[2]), "=r"(r[3]) : "r"(addr));
}
__device__ __forceinline__ void mma16816(float* d, const uint32_t* a, const uint32_t* b) {
    asm volatile(
        "mma.sync.aligned.m16n8k16.row.col.f32.f16.f16.f32 "
        "{%0,%1,%2,%3}, {%4,%5,%6,%7}, {%8,%9}, {%0,%1,%2,%3};"
        : "+f"(d[0]), "+f"(d[1]), "+f"(d[2]), "+f"(d[3])
        : "r"(a[0]), "r"(a[1]), "r"(a[2]), "r"(a[3]), "r"(b[0]), "r"(b[1]));
}
__device__ __forceinline__ float ex2(float x) {
    float y;
    asm("ex2.approx.f32 %0, %1;" : "=f"(y) : "f"(x));
    return y;
}

constexpr int LDS_H       = 136;                  // halves per smem row (pad 8)
constexpr int TILE_HALVES = 128 * LDS_H;
constexpr int TILE_BYTES2 = TILE_HALVES * 2;      // 34816
constexpr int BUF_BYTES   = 2 * TILE_HALVES * 2;  // A+B one buffer = 69632 B

// ---------------- HMMA GEMM (final projection; EPI 4 = + bias[m] + res) ------
template <typename OutT, int EPI>
__global__ __launch_bounds__(256) void hgemm_nt(
    const __half* __restrict__ A, const __half* __restrict__ B, OutT* __restrict__ C,
    const float* __restrict__ bias, const float* __restrict__ res,
    int kchunks, int lda, int ldb, int ldc,
    long sAo, long sAi, long sBo, long sBi, long sCo, long sCi,
    int zH, float alpha)
{
    extern __shared__ __half smh[];
    const uint32_t sbase = smem_u32(smh);

    const int z  = blockIdx.z;
    const int zo = z / zH, zi = z % zH;
    const int m0 = blockIdx.y * 128, n0 = blockIdx.x * 128;
    A += (size_t)zo * sAo + (size_t)zi * sAi + (size_t)m0 * lda;
    B += (size_t)zo * sBo + (size_t)zi * sBi + (size_t)n0 * ldb;
    const size_t coff = (size_t)zo * sCo + (size_t)zi * sCi + (size_t)m0 * ldc + n0;
    C += coff;
    const float* R = res;
    if (EPI == 4) R += coff;

    const int tid  = threadIdx.x;
    const int lane = tid & 31;
    const int wid  = tid >> 5;
    const int wm   = (wid & 3) * 32;
    const int wn   = (wid >> 2) * 64;

    auto loadc = [&](int buf, int kofs) {
        const uint32_t ab = sbase + (uint32_t)buf * BUF_BYTES;
        const uint32_t bb = ab + TILE_BYTES2;
#pragma unroll
        for (int i = 0; i < 8; i++) {
            int idx = i * 256 + tid;
            int row = idx >> 4;
            int col = (idx & 15) * 8;
            cp16(ab + (uint32_t)(row * LDS_H + col) * 2, A + (size_t)row * lda + kofs + col);
            cp16(bb + (uint32_t)(row * LDS_H + col) * 2, B + (size_t)row * ldb + kofs + col);
        }
        cp_commit();
    };

    float acc[2][8][4] = {};

    loadc(0, 0);
    for (int kc = 0; kc < kchunks; kc++) {
        if (kc + 1 < kchunks) { loadc((kc + 1) & 1, (kc + 1) * 128); cp_wait1(); }
        else                  { cp_wait0(); }
        __syncthreads();

        const uint32_t ab = sbase + (uint32_t)(kc & 1) * BUF_BYTES;
        const uint32_t bb = ab + TILE_BYTES2;

#pragma unroll
        for (int ks = 0; ks < 8; ks++) {
            const int k0 = ks * 16;
            uint32_t af[2][4];
#pragma unroll
            for (int mf = 0; mf < 2; mf++) {
                int m  = wm + mf * 16 + (lane & 15);
                int kk = k0 + (lane >> 4) * 8;
                ldsm4(af[mf], ab + (uint32_t)(m * LDS_H + kk) * 2);
            }
            uint32_t bf[8][2];
#pragma unroll
            for (int p = 0; p < 4; p++) {
                int nrow = wn + p * 16 + ((lane >> 4) & 1) * 8 + (lane & 7);
                int kk   = k0 + ((lane >> 3) & 1) * 8;
                uint32_t r[4];
                ldsm4(r, bb + (uint32_t)(nrow * LDS_H + kk) * 2);
                bf[2 * p][0] = r[0]; bf[2 * p][1] = r[1];
                bf[2 * p + 1][0] = r[2]; bf[2 * p + 1][1] = r[3];
            }
#pragma unroll
            for (int mf = 0; mf < 2; mf++)
#pragma unroll
                for (int nf = 0; nf < 8; nf++)
                    mma16816(acc[mf][nf], af[mf], bf[nf]);
        }
        __syncthreads();
    }

#pragma unroll
    for (int mf = 0; mf < 2; mf++) {
#pragma unroll
        for (int nf = 0; nf < 8; nf++) {
            int m = wm + mf * 16 + (lane >> 2);
            int n = wn + nf * 8 + (lane & 3) * 2;
            float v0 = acc[mf][nf][0] * alpha, v1 = acc[mf][nf][1] * alpha;
            float v2 = acc[mf][nf][2] * alpha, v3 = acc[mf][nf][3] * alpha;
            if (EPI == 2 || EPI == 4) {
                float bm0 = bias[m0 + m], bm1 = bias[m0 + m + 8];
                v0 += bm0; v1 += bm0; v2 += bm1; v3 += bm1;
            }
            if (EPI == 4) {
                float2 r0 = *(const float2*)(R + (size_t)m * ldc + n);
                float2 r1 = *(const float2*)(R + (size_t)(m + 8) * ldc + n);
                v0 += r0.x; v1 += r0.y; v2 += r1.x; v3 += r1.y;
            }
            if (sizeof(OutT) == 2) {
                *(__half2*)((__half*)C + (size_t)m * ldc + n)       = __floats2half2_rn(v0, v1);
                *(__half2*)((__half*)C + (size_t)(m + 8) * ldc + n) = __floats2half2_rn(v2, v3);
            } else {
                *(float2*)((float*)C + (size_t)m * ldc + n)       = make_float2(v0, v1);
                *(float2*)((float*)C + (size_t)(m + 8) * ldc + n) = make_float2(v2, v3);
            }
        }
    }
}

// ---------------- fused QKV projection (128x256 CTA tile, 64x64 warp tiles) ----
constexpr int PJ_X     = 0;                            // 128 x 136 x 2 = 34816
constexpr int PJ_W     = TILE_BYTES2;                  // two 256x136x2 buffers
constexpr int PJ_WSZ   = 256 * LDS_H * 2;              // 69632
constexpr int PJ_SMEM  = PJ_W + 2 * PJ_WSZ;            // 174080 B

__global__ __launch_bounds__(256, 1) void proj_k() {
    extern __shared__ __half psm[];
    char* smc = (char*)psm;
    const uint32_t sb = smem_u32(psm);
    const int tid = threadIdx.x, lane = tid & 31, wid = tid >> 5;
    const int p0 = blockIdx.x * 128;
    const int b  = blockIdx.y;

    const __half* X = g_xh + ((size_t)b * NP + p0) * NC;
    __half* Oqk = g_qkh + ((size_t)b * NP + p0) * NQK;

    const int wm = (wid & 1) * 64;      // 0 or 64
    const int wn = (wid >> 1) * 64;     // 0,64,128,192

#pragma unroll
    for (int i = 0; i < 8; i++) {
        int idx = i * 256 + tid, row = idx >> 4, col = (idx & 15) * 8;
        cp16(sb + PJ_X + (uint32_t)(row * LDS_H + col) * 2, X + (size_t)row * NC + col);
    }
    auto loadW = [&](int buf, int nt) {
        const uint32_t wb = sb + PJ_W + (uint32_t)buf * PJ_WSZ;
        const __half* W = g_wqkv + (size_t)nt * 256 * NC;
#pragma unroll
        for (int i = 0; i < 16; i++) {
            int idx = i * 256 + tid, row = idx >> 4, col = (idx & 15) * 8;
            cp16(wb + (uint32_t)(row * LDS_H + col) * 2, W + (size_t)row * NC + col);
        }
        cp_commit();
    };
    loadW(0, 0);

    float acc[4][8][4];

    auto compute = [&](uint32_t wb) {
#pragma unroll
        for (int mf = 0; mf < 4; mf++)
#pragma unroll
            for (int nf = 0; nf < 8; nf++)
#pragma unroll
                for (int q = 0; q < 4; q++) acc[mf][nf][q] = 0.f;
#pragma unroll
        for (int ks = 0; ks < 8; ks++) {
            const int k0 = ks * 16;
            uint32_t af[4][4];
#pragma unroll
            for (int mf = 0; mf < 4; mf++) {
                int m  = wm + mf * 16 + (lane & 15);
                int kk = k0 + (lane >> 4) * 8;
                ldsm4(af[mf], sb + PJ_X + (uint32_t)(m * LDS_H + kk) * 2);
            }
            uint32_t bf[8][2];
#pragma unroll
            for (int p = 0; p < 4; p++) {
                int nrow = wn + p * 16 + ((lane >> 4) & 1) * 8 + (lane & 7);
                int kk   = k0 + ((lane >> 3) & 1) * 8;
                uint32_t r[4];
                ldsm4(r, wb + (uint32_t)(nrow * LDS_H + kk) * 2);
                bf[2 * p][0] = r[0]; bf[2 * p][1] = r[1];
                bf[2 * p + 1][0] = r[2]; bf[2 * p + 1][1] = r[3];
            }
#pragma unroll
            for (int mf = 0; mf < 4; mf++)
#pragma unroll
                for (int nf = 0; nf < 8; nf++)
                    mma16816(acc[mf][nf], af[mf], bf[nf]);
        }
    };

    for (int nt = 0; nt < 4; nt++) {
        loadW((nt + 1) & 1, nt + 1);
        cp_wait1();
        __syncthreads();
        compute(sb + PJ_W + (uint32_t)(nt & 1) * PJ_WSZ);
#pragma unroll
        for (int mf = 0; mf < 4; mf++) {
#pragma unroll
            for (int nf = 0; nf < 8; nf++) {
                int m = wm + mf * 16 + (lane >> 2);
                int n = nt * 256 + wn + nf * 8 + (lane & 3) * 2;
                float b0 = g_bqkv[n], b1 = g_bqkv[n + 1];
                *(__half2*)(Oqk + (size_t)m * NQK + n) =
                    __floats2half2_rn(acc[mf][nf][0] + b0, acc[mf][nf][1] + b1);
                *(__half2*)(Oqk + (size_t)(m + 8) * NQK + n) =
                    __floats2half2_rn(acc[mf][nf][2] + b0, acc[mf][nf][3] + b1);
            }
        }
        __syncthreads();
    }

    for (int vt = 0; vt < 2; vt++) {
        const uint32_t wcomp = sb + PJ_W;
        if (vt == 0) cp_wait0();
        __syncthreads();
        compute(wcomp);
        __syncthreads();
        if (vt == 0) loadW(0, 5);
        __half* st = (__half*)(smc + PJ_W + PJ_WSZ);
#pragma unroll
        for (int mf = 0; mf < 4; mf++) {
#pragma unroll
            for (int nf = 0; nf < 8; nf++) {
                int m = wm + mf * 16 + (lane >> 2);
                int n = wn + nf * 8 + (lane & 3) * 2;
                float b0 = g_bqkv[1024 + vt * 256 + n];
                float b1 = g_bqkv[1024 + vt * 256 + n + 1];
                st[(size_t)n * LDS_H + m]           = __float2half(acc[mf][nf][0] + b0);
                st[(size_t)(n + 1) * LDS_H + m]     = __float2half(acc[mf][nf][1] + b1);
                st[(size_t)n * LDS_H + m + 8]       = __float2half(acc[mf][nf][2] + b0);
                st[(size_t)(n + 1) * LDS_H + m + 8] = __float2half(acc[mf][nf][3] + b1);
            }
        }
        __syncthreads();
        __half* Vout = g_vh + ((size_t)b * NCH + (size_t)vt * 256) * NP + p0;
#pragma unroll
        for (int i = 0; i < 16; i++) {
            int idx = i * 256 + tid, row = idx >> 4, col = (idx & 15) * 8;
            uint4 v = *(uint4*)(smc + PJ_W + PJ_WSZ + (uint32_t)(row * LDS_H + col) * 2);
            *(uint4*)(Vout + (size_t)row * NP + col) = v;
        }
        if (vt == 0) { cp_wait0(); }
        __syncthreads();
    }
}

// ---------------- fused flash attention v2b: m32 warps, S in n-halves ----------
// 8 warps x 32 query rows (CTA i-tile 256). S-phase now runs in n-halves of 64
// (sq transient 64 regs) so Q A-frags are re-read 2x per kc instead of 4x:
// per-warp crossbar traffic drops 96 KB -> 80 KB per kc. O-phase unchanged
// (V B-frags shared across both m-frags = 128 B/MMA optimum).
constexpr int FQ_ROWS = 256;
constexpr int FQ_BYTES = FQ_ROWS * LDS_H * 2;          // 69632
constexpr int FKV0     = FQ_BYTES;                     // 2 x (K,V) buffers
constexpr int FSMEM    = FKV0 + 4 * TILE_BYTES2;       // 208896 B

__global__ __launch_bounds__(256, 1) void flash_k() {
    extern __shared__ __half fsm[];
    const uint32_t sb = smem_u32(fsm);
    const int tid = threadIdx.x, lane = tid & 31, wid = tid >> 5;
    const int i0 = blockIdx.x * FQ_ROWS;
    const int z  = blockIdx.y;
    const int b  = z >> 2, h = z & 3;

    const __half* Qg = g_qkh + ((size_t)b * NP + i0) * NQK + h * 128;
    const __half* Kg = g_qkh + (size_t)b * NP * NQK + 512 + h * 128;
    const __half* Vg = g_vh  + (size_t)b * NCH * NP + (size_t)h * 128 * NP;

    // Q tile (256 rows) -> smem, joins group 0 with first KV load
#pragma unroll
    for (int i = 0; i < 16; i++) {
        int idx = i * 256 + tid, row = idx >> 4, col = (idx & 15) * 8;
        cp16(sb + (uint32_t)(row * LDS_H + col) * 2, Qg + (size_t)row * NQK + col);
    }
    auto loadKV = [&](int buf, int j0) {
        uint32_t kb = sb + FKV0 + (uint32_t)buf * 2 * TILE_BYTES2;
        uint32_t vb = kb + TILE_BYTES2;
#pragma unroll
        for (int i = 0; i < 8; i++) {
            int idx = i * 256 + tid, row = idx >> 4, col = (idx & 15) * 8;
            cp16(kb + (uint32_t)(row * LDS_H + col) * 2, Kg + (size_t)(j0 + row) * NQK + col);
            cp16(vb + (uint32_t)(row * LDS_H + col) * 2, Vg + (size_t)row * NP + j0 + col);
        }
        cp_commit();
    };
    loadKV(0, 0);

    const int wm = wid * 32;            // warp's 32 query rows
    uint32_t Pf[2][8][4];               // packed P: [mf][jstep][frag]
    float oacc[2][16][4] = {};          // [mf][ch-frag][quad]
    float l00 = 0.f, l01 = 0.f, l10 = 0.f, l11 = 0.f;   // l[mf][rowpair]

    for (int kc = 0; kc < 16; kc++) {
        if (kc + 1 < 16) { loadKV((kc + 1) & 1, (kc + 1) * 128); cp_wait1(); }
        else             { cp_wait0(); }
        __syncthreads();
        const uint32_t kb = sb + FKV0 + (uint32_t)(kc & 1) * 2 * TILE_BYTES2;
        const uint32_t vb = kb + TILE_BYTES2;

        // ---- S phase in n-halves of 64; exp+pack into Pf ----
#pragma unroll
        for (int nh = 0; nh < 2; nh++) {
            float sq[2][8][4];
#pragma unroll
            for (int mf = 0; mf < 2; mf++)
#pragma unroll
                for (int nf = 0; nf < 8; nf++)
#pragma unroll
                    for (int q = 0; q < 4; q++) sq[mf][nf][q] = 0.f;
#pragma unroll
            for (int ks = 0; ks < 8; ks++) {
                const int k0 = ks * 16;
                uint32_t af[2][4];
#pragma unroll
                for (int mf = 0; mf < 2; mf++) {
                    int m  = wm + mf * 16 + (lane & 15);
                    int kk = k0 + (lane >> 4) * 8;
                    ldsm4(af[mf], sb + (uint32_t)(m * LDS_H + kk) * 2);
                }
                uint32_t bf[8][2];
#pragma unroll
                for (int p = 0; p < 4; p++) {
                    int nrow = nh * 64 + p * 16 + ((lane >> 4) & 1) * 8 + (lane & 7);
                    int kk   = k0 + ((lane >> 3) & 1) * 8;
                    uint32_t r[4];
                    ldsm4(r, kb + (uint32_t)(nrow * LDS_H + kk) * 2);
                    bf[2 * p][0] = r[0]; bf[2 * p][1] = r[1];
                    bf[2 * p + 1][0] = r[2]; bf[2 * p + 1][1] = r[3];
                }
#pragma unroll
                for (int mf = 0; mf < 2; mf++)
#pragma unroll
                    for (int nf = 0; nf < 8; nf++)
                        mma16816(sq[mf][nf], af[mf], bf[nf]);
            }
            // exp + l + pack (jsteps 4*nh .. 4*nh+3)
#pragma unroll
            for (int mf = 0; mf < 2; mf++) {
#pragma unroll
                for (int lj = 0; lj < 4; lj++) {
                    float p0 = ex2(sq[mf][2 * lj][0]),     p1 = ex2(sq[mf][2 * lj][1]);
                    float p2 = ex2(sq[mf][2 * lj][2]),     p3 = ex2(sq[mf][2 * lj][3]);
                    float p4 = ex2(sq[mf][2 * lj + 1][0]), p5 = ex2(sq[mf][2 * lj + 1][1]);
                    float p6 = ex2(sq[mf][2 * lj + 1][2]), p7 = ex2(sq[mf][2 * lj + 1][3]);
                    if (mf == 0) { l00 += p0 + p1 + p4 + p5; l01 += p2 + p3 + p6 + p7; }
                    else         { l10 += p0 + p1 + p4 + p5; l11 += p2 + p3 + p6 + p7; }
                    __half2 h01 = __floats2half2_rn(p0, p1);
                    __half2 h23 = __floats2half2_rn(p2, p3);
                    __half2 h45 = __floats2half2_rn(p4, p5);
                    __half2 h67 = __floats2half2_rn(p6, p7);
                    Pf[mf][4 * nh + lj][0] = *(uint32_t*)&h01;
                    Pf[mf][4 * nh + lj][1] = *(uint32_t*)&h23;
                    Pf[mf][4 * nh + lj][2] = *(uint32_t*)&h45;
                    Pf[mf][4 * nh + lj][3] = *(uint32_t*)&h67;
                }
            }
        }

        // ---- O phase: oacc += P * V^T ----
#pragma unroll
        for (int js = 0; js < 8; js++) {
            uint32_t bfv[16][2];
#pragma unroll
            for (int p = 0; p < 8; p++) {
                int nrow = p * 16 + ((lane >> 4) & 1) * 8 + (lane & 7);
                int kk   = js * 16 + ((lane >> 3) & 1) * 8;
                uint32_t r[4];
                ldsm4(r, vb + (uint32_t)(nrow * LDS_H + kk) * 2);
                bfv[2 * p][0] = r[0]; bfv[2 * p][1] = r[1];
                bfv[2 * p + 1][0] = r[2]; bfv[2 * p + 1][1] = r[3];
            }
#pragma unroll
            for (int mf = 0; mf < 2; mf++)
#pragma unroll
                for (int nf = 0; nf < 16; nf++)
                    mma16816(oacc[mf][nf], Pf[mf][js], bfv[nf]);
        }
        __syncthreads();   // done reading buffer before next prefetch overwrites
    }

    // ---- epilogue: quad-reduce l, normalize, write att ----
    l00 += __shfl_xor_sync(0xffffffffu, l00, 1);
    l00 += __shfl_xor_sync(0xffffffffu, l00, 2);
    l01 += __shfl_xor_sync(0xffffffffu, l01, 1);
    l01 += __shfl_xor_sync(0xffffffffu, l01, 2);
    l10 += __shfl_xor_sync(0xffffffffu, l10, 1);
    l10 += __shfl_xor_sync(0xffffffffu, l10, 2);
    l11 += __shfl_xor_sync(0xffffffffu, l11, 1);
    l11 += __shfl_xor_sync(0xffffffffu, l11, 2);
    float inv[2][2] = { {1.f / l00, 1.f / l01}, {1.f / l10, 1.f / l11} };
    __half* ob = g_ath + (size_t)b * NP * NCH;
#pragma unroll
    for (int mf = 0; mf < 2; mf++) {
        const int row0 = i0 + wm + mf * 16 + (lane >> 2);
#pragma unroll
        for (int nf = 0; nf < 16; nf++) {
            int col = h * 128 + nf * 8 + (lane & 3) * 2;
            *(__half2*)(ob + (size_t)row0 * NCH + col) =
                __floats2half2_rn(oacc[mf][nf][0] * inv[mf][0],
                                  oacc[mf][nf][1] * inv[mf][0]);
            *(__half2*)(ob + (size_t)(row0 + 8) * NCH + col) =
                __floats2half2_rn(oacc[mf][nf][2] * inv[mf][1],
                                  oacc[mf][nf][3] * inv[mf][1]);
        }
    }
}

// ---------------- batchnorm statistics ---------------------------------------
__global__ __launch_bounds__(256) void bn_stats_k(const float* __restrict__ in,
                                                  const float* __restrict__ gamma,
                                                  const float* __restrict__ beta) {
    const int c = blockIdx.x;
    const int t = threadIdx.x;
    float s = 0.f, ss = 0.f;
    for (int idx = t; idx < NB * NP; idx += 256) {
        int b = idx >> 11;
        int p = idx & (NP - 1);
        float v = in[(size_t)b * NC * NP + (size_t)c * NP + p];
        s += v; ss += v * v;
    }
    __shared__ float r1[256], r2[256];
    r1[t] = s; r2[t] = ss;
    __syncthreads();
    for (int off = 128; off > 0; off >>= 1) {
        if (t < off) { r1[t] += r1[t + off]; r2[t] += r2[t + off]; }
        __syncthreads();
    }
    if (t == 0) {
        const float invN = 1.f / (NB * NP);
        float mean = r1[0] * invN;
        float var  = r2[0] * invN - mean * mean;
        float rstd = rsqrtf(var + 1e-5f);
        float sc = gamma[c] * rstd;
        g_scale[c] = sc;
        g_shift[c] = beta[c] - mean * sc;
    }
}

// ---------------- normalize + transpose: [b][c][p] f32 -> [b][p][c] half -------
__global__ __launch_bounds__(256) void norm_t_k(const float* __restrict__ in) {
    const int b = blockIdx.z;
    const int c0 = blockIdx.y * 32, p0 = blockIdx.x * 32;
    const int tx = threadIdx.x & 31, ty = threadIdx.x >> 5;   // 32 x 8
    __shared__ float s[32][33];
#pragma unroll
    for (int j = 0; j < 4; j++) {
        int c = c0 + ty + j * 8;
        float v = in[((size_t)b * NC + c) * NP + p0 + tx];
        s[ty + j * 8][tx] = v * g_scale[c] + g_shift[c];
    }
    __syncthreads();
#pragma unroll
    for (int j = 0; j < 4; j++) {
        int p = p0 + ty + j * 8;
        g_xh[((size_t)b * NP + p) * NC + c0 + tx] = __float2half(s[tx][ty + j * 8]);
    }
}

// ---------------- weight prep --------------------------------------------------
__global__ __launch_bounds__(256) void wprep_k(
    const float* __restrict__ Wq, const float* __restrict__ bq,
    const float* __restrict__ Wk, const float* __restrict__ bk,
    const float* __restrict__ Wv, const float* __restrict__ bv,
    const float* __restrict__ Wo)
{
    const float CE = 0.08838834764831845f * 1.4426950408889634f;
    int idx = blockIdx.x * 256 + threadIdx.x;   // 0..262143
    if (idx < 196608) {
        int o = idx >> 7, c = idx & 127;
        int sect = o >> 9;              // 0=q 1=k 2=v
        int op = o & 511, h = op >> 7, cp = op & 127;
        const float* W = (sect == 0) ? Wq : (sect == 1) ? Wk : Wv;
        float scale = (sect == 0) ? CE : 1.f;
        g_wqkv[idx] = __float2half(W[(cp * 4 + h) * 128 + c] * scale);
    } else {
        int t = idx - 196608;
        int o2 = t >> 9, op = t & 511;
        int h = op >> 7, cp = op & 127;
        g_wo[t] = __float2half(Wo[o2 * 512 + cp * 4 + h]);
    }
    if (idx < 1536) {
        int sect = idx >> 9, op = idx & 511, h = op >> 7, cp = op & 127;
        const float* bb = (sect == 0) ? bq : (sect == 1) ? bk : bv;
        float scale = (sect == 0) ? CE : 1.f;
        g_bqkv[idx] = bb[cp * 4 + h] * scale;
    }
}

// ---------------- launch ------------------------------------------------------
extern "C" void kernel_launch(void* const* d_in, const int* in_sizes, int n_in,
                              void* d_out, int out_size) {
    const float* input = (const float*)d_in[0];
    const float* gamma = (const float*)d_in[1];
    const float* beta  = (const float*)d_in[2];
    const float* Wq    = (const float*)d_in[3];
    const float* bq    = (const float*)d_in[4];
    const float* Wk    = (const float*)d_in[5];
    const float* bk    = (const float*)d_in[6];
    const float* Wv    = (const float*)d_in[7];
    const float* bv    = (const float*)d_in[8];
    const float* Wo    = (const float*)d_in[9];
    const float* bo    = (const float*)d_in[10];
    float* out = (float*)d_out;

    __half *pwo, *path;
    cudaGetSymbolAddress((void**)&pwo,  g_wo);
    cudaGetSymbolAddress((void**)&path, g_ath);

    cudaFuncSetAttribute(hgemm_nt<float, 4>, cudaFuncAttributeMaxDynamicSharedMemorySize, 2 * BUF_BYTES);
    cudaFuncSetAttribute(proj_k,  cudaFuncAttributeMaxDynamicSharedMemorySize, PJ_SMEM);
    cudaFuncSetAttribute(flash_k, cudaFuncAttributeMaxDynamicSharedMemorySize, FSMEM);

    // 1) batchnorm stats, normalize+transpose, weight prep
    bn_stats_k<<<NC, 256>>>(input, gamma, beta);
    wprep_k<<<1024, 256>>>(Wq, bq, Wk, bk, Wv, bv, Wo);
    norm_t_k<<<dim3(NP / 32, NC / 32, NB), 256>>>(input);

    // 2) fused QKV projection -> qk[b][p][1024], v[b][(h,c')][p]
    proj_k<<<dim3(NP / 128, NB), 256, PJ_SMEM>>>();

    // 3) fused attention v2b: 256-row i-tiles, m32 warps, S in n-halves
    flash_k<<<dim3(NP / FQ_ROWS, NZ), 256, FSMEM>>>();

    // 4) out = Wo' att + bo + input : M=128 N=2048 K=512 per batch
    hgemm_nt<float, 4><<<dim3(16, 1, NB), 256, 2 * BUF_BYTES>>>(
        pwo, path, out, bo, input,
        4, NCH, NCH, NP,
        0, 0, (long)NP * NCH, 0, (long)NC * NP, 0, 1, 1.f);
}

// round 17
// speedup vs baseline: 1.0808x; 1.0808x over previous
#include <cuda_runtime.h>
#include <cuda_fp16.h>
#include <cstdint>
#include <math.h>

// Problem constants
constexpr int NB  = 8;     // batch
constexpr int NC  = 128;   // channels
constexpr int NP  = 2048;  // points
constexpr int NH  = 4;     // heads
constexpr int NCH = 512;   // c*h
constexpr int NZ  = NB * NH;  // 32 (b,h) slices
constexpr int NQK = 1024;  // q|k packed output width

// ---------------- scratch (static device globals; no allocation) -------------
__device__ __align__(1024) float  g_scale[NC];
__device__ __align__(1024) float  g_shift[NC];
__device__ __align__(1024) __half g_xh  [NB * NP * NC];        // x half [b][p][c]
__device__ __align__(1024) __half g_wqkv[1536 * 128];          // [(q|k|v)(h,c')][c]
__device__ __align__(1024) __half g_wo  [128 * 512];           // [c][(h,c')]
__device__ __align__(1024) float  g_bqkv[1536];
__device__ __align__(1024) __half g_qkh [NB * NP * NQK];       // [b][p][q|k (h,c')]
__device__ __align__(1024) __half g_vh  [NB * NCH * NP];       // [b][(h,c')][p]
__device__ __align__(1024) __half g_ath [NB * NP * NCH];       // [b][p][(h,c')]

// =================== PTX helpers =============================================
__device__ __forceinline__ uint32_t smem_u32(const void* p) {
    uint32_t a;
    asm("{ .reg .u64 t; cvta.to.shared.u64 t, %1; cvt.u32.u64 %0, t; }" : "=r"(a) : "l"(p));
    return a;
}
__device__ __forceinline__ void cp16(uint32_t s, const void* g) {
    asm volatile("cp.async.cg.shared.global [%0], [%1], 16;" :: "r"(s), "l"(g));
}
__device__ __forceinline__ void cp_commit() { asm volatile("cp.async.commit_group;"); }
__device__ __forceinline__ void cp_wait0()  { asm volatile("cp.async.wait_group 0;"); }
__device__ __forceinline__ void cp_wait1()  { asm volatile("cp.async.wait_group 1;"); }
__device__ __forceinline__ void ldsm4(uint32_t* r, uint32_t addr) {
    asm volatile("ldmatrix.sync.aligned.m8n8.x4.shared.b16 {%0,%1,%2,%3}, [%4];"
                 : "=r"(r[0]), "=r"(r[1]), "=r"(r[2]), "=r"(r[3]) : "r"(addr));
}
__device__ __forceinline__ void mma16816(float* d, const uint32_t* a, const uint32_t* b) {
    asm volatile(
        "mma.sync.aligned.m16n8k16.row.col.f32.f16.f16.f32 "
        "{%0,%1,%2,%3}, {%4,%5,%6,%7}, {%8,%9}, {%0,%1,%2,%3};"
        : "+f"(d[0]), "+f"(d[1]), "+f"(d[2]), "+f"(d[3])
        : "r"(a[0]), "r"(a[1]), "r"(a[2]), "r"(a[3]), "r"(b[0]), "r"(b[1]));
}
__device__ __forceinline__ float ex2(float x) {
    float y;
    asm("ex2.approx.f32 %0, %1;" : "=f"(y) : "f"(x));
    return y;
}

constexpr int LDS_H       = 136;                  // halves per smem row (pad 8)
constexpr int TILE_HALVES = 128 * LDS_H;
constexpr int TILE_BYTES2 = TILE_HALVES * 2;      // 34816
constexpr int BUF_BYTES   = 2 * TILE_HALVES * 2;  // A+B one buffer = 69632 B

// ---------------- HMMA GEMM (final projection; EPI 4 = + bias[m] + res) ------
template <typename OutT, int EPI>
__global__ __launch_bounds__(256) void hgemm_nt(
    const __half* __restrict__ A, const __half* __restrict__ B, OutT* __restrict__ C,
    const float* __restrict__ bias, const float* __restrict__ res,
    int kchunks, int lda, int ldb, int ldc,
    long sAo, long sAi, long sBo, long sBi, long sCo, long sCi,
    int zH, float alpha)
{
    extern __shared__ __half smh[];
    const uint32_t sbase = smem_u32(smh);

    const int z  = blockIdx.z;
    const int zo = z / zH, zi = z % zH;
    const int m0 = blockIdx.y * 128, n0 = blockIdx.x * 128;
    A += (size_t)zo * sAo + (size_t)zi * sAi + (size_t)m0 * lda;
    B += (size_t)zo * sBo + (size_t)zi * sBi + (size_t)n0 * ldb;
    const size_t coff = (size_t)zo * sCo + (size_t)zi * sCi + (size_t)m0 * ldc + n0;
    C += coff;
    const float* R = res;
    if (EPI == 4) R += coff;

    const int tid  = threadIdx.x;
    const int lane = tid & 31;
    const int wid  = tid >> 5;
    const int wm   = (wid & 3) * 32;
    const int wn   = (wid >> 2) * 64;

    auto loadc = [&](int buf, int kofs) {
        const uint32_t ab = sbase + (uint32_t)buf * BUF_BYTES;
        const uint32_t bb = ab + TILE_BYTES2;
#pragma unroll
        for (int i = 0; i < 8; i++) {
            int idx = i * 256 + tid;
            int row = idx >> 4;
            int col = (idx & 15) * 8;
            cp16(ab + (uint32_t)(row * LDS_H + col) * 2, A + (size_t)row * lda + kofs + col);
            cp16(bb + (uint32_t)(row * LDS_H + col) * 2, B + (size_t)row * ldb + kofs + col);
        }
        cp_commit();
    };

    float acc[2][8][4] = {};

    loadc(0, 0);
    for (int kc = 0; kc < kchunks; kc++) {
        if (kc + 1 < kchunks) { loadc((kc + 1) & 1, (kc + 1) * 128); cp_wait1(); }
        else                  { cp_wait0(); }
        __syncthreads();

        const uint32_t ab = sbase + (uint32_t)(kc & 1) * BUF_BYTES;
        const uint32_t bb = ab + TILE_BYTES2;

#pragma unroll
        for (int ks = 0; ks < 8; ks++) {
            const int k0 = ks * 16;
            uint32_t af[2][4];
#pragma unroll
            for (int mf = 0; mf < 2; mf++) {
                int m  = wm + mf * 16 + (lane & 15);
                int kk = k0 + (lane >> 4) * 8;
                ldsm4(af[mf], ab + (uint32_t)(m * LDS_H + kk) * 2);
            }
            uint32_t bf[8][2];
#pragma unroll
            for (int p = 0; p < 4; p++) {
                int nrow = wn + p * 16 + ((lane >> 4) & 1) * 8 + (lane & 7);
                int kk   = k0 + ((lane >> 3) & 1) * 8;
                uint32_t r[4];
                ldsm4(r, bb + (uint32_t)(nrow * LDS_H + kk) * 2);
                bf[2 * p][0] = r[0]; bf[2 * p][1] = r[1];
                bf[2 * p + 1][0] = r[2]; bf[2 * p + 1][1] = r[3];
            }
#pragma unroll
            for (int mf = 0; mf < 2; mf++)
#pragma unroll
                for (int nf = 0; nf < 8; nf++)
                    mma16816(acc[mf][nf], af[mf], bf[nf]);
        }
        __syncthreads();
    }

#pragma unroll
    for (int mf = 0; mf < 2; mf++) {
#pragma unroll
        for (int nf = 0; nf < 8; nf++) {
            int m = wm + mf * 16 + (lane >> 2);
            int n = wn + nf * 8 + (lane & 3) * 2;
            float v0 = acc[mf][nf][0] * alpha, v1 = acc[mf][nf][1] * alpha;
            float v2 = acc[mf][nf][2] * alpha, v3 = acc[mf][nf][3] * alpha;
            if (EPI == 2 || EPI == 4) {
                float bm0 = bias[m0 + m], bm1 = bias[m0 + m + 8];
                v0 += bm0; v1 += bm0; v2 += bm1; v3 += bm1;
            }
            if (EPI == 4) {
                float2 r0 = *(const float2*)(R + (size_t)m * ldc + n);
                float2 r1 = *(const float2*)(R + (size_t)(m + 8) * ldc + n);
                v0 += r0.x; v1 += r0.y; v2 += r1.x; v3 += r1.y;
            }
            if (sizeof(OutT) == 2) {
                *(__half2*)((__half*)C + (size_t)m * ldc + n)       = __floats2half2_rn(v0, v1);
                *(__half2*)((__half*)C + (size_t)(m + 8) * ldc + n) = __floats2half2_rn(v2, v3);
            } else {
                *(float2*)((float*)C + (size_t)m * ldc + n)       = make_float2(v0, v1);
                *(float2*)((float*)C + (size_t)(m + 8) * ldc + n) = make_float2(v2, v3);
            }
        }
    }
}

// ---------------- fused QKV projection (128x256 CTA, m-split compute) ----------
// Grid (16 p-tiles, 8 b). 8 warps as 2m x 4n (warp tile 64x64), but compute is
// split into two sequential 32-row passes so the live accumulator is 64 regs
// (no spills; R15 version capped at 255 regs and spilled).
constexpr int PJ_X     = 0;                            // 128 x 136 x 2 = 34816
constexpr int PJ_W     = TILE_BYTES2;                  // two 256x136x2 buffers
constexpr int PJ_WSZ   = 256 * LDS_H * 2;              // 69632
constexpr int PJ_SMEM  = PJ_W + 2 * PJ_WSZ;            // 174080 B

__global__ __launch_bounds__(256, 1) void proj_k() {
    extern __shared__ __half psm[];
    char* smc = (char*)psm;
    const uint32_t sb = smem_u32(psm);
    const int tid = threadIdx.x, lane = tid & 31, wid = tid >> 5;
    const int p0 = blockIdx.x * 128;
    const int b  = blockIdx.y;

    const __half* X = g_xh + ((size_t)b * NP + p0) * NC;
    __half* Oqk = g_qkh + ((size_t)b * NP + p0) * NQK;

    const int wm = (wid & 1) * 64;      // 0 or 64
    const int wn = (wid >> 1) * 64;     // 0,64,128,192

#pragma unroll
    for (int i = 0; i < 8; i++) {
        int idx = i * 256 + tid, row = idx >> 4, col = (idx & 15) * 8;
        cp16(sb + PJ_X + (uint32_t)(row * LDS_H + col) * 2, X + (size_t)row * NC + col);
    }
    auto loadW = [&](int buf, int nt) {
        const uint32_t wb = sb + PJ_W + (uint32_t)buf * PJ_WSZ;
        const __half* W = g_wqkv + (size_t)nt * 256 * NC;
#pragma unroll
        for (int i = 0; i < 16; i++) {
            int idx = i * 256 + tid, row = idx >> 4, col = (idx & 15) * 8;
            cp16(wb + (uint32_t)(row * LDS_H + col) * 2, W + (size_t)row * NC + col);
        }
        cp_commit();
    };
    loadW(0, 0);

    float acc[2][8][4];

    // compute one 32-row m-half of the warp's 64x64 tile
    auto compute = [&](uint32_t wb, int mh) {
#pragma unroll
        for (int mf = 0; mf < 2; mf++)
#pragma unroll
            for (int nf = 0; nf < 8; nf++)
#pragma unroll
                for (int q = 0; q < 4; q++) acc[mf][nf][q] = 0.f;
#pragma unroll
        for (int ks = 0; ks < 8; ks++) {
            const int k0 = ks * 16;
            uint32_t af[2][4];
#pragma unroll
            for (int mf = 0; mf < 2; mf++) {
                int m  = wm + mh * 32 + mf * 16 + (lane & 15);
                int kk = k0 + (lane >> 4) * 8;
                ldsm4(af[mf], sb + PJ_X + (uint32_t)(m * LDS_H + kk) * 2);
            }
            uint32_t bf[8][2];
#pragma unroll
            for (int p = 0; p < 4; p++) {
                int nrow = wn + p * 16 + ((lane >> 4) & 1) * 8 + (lane & 7);
                int kk   = k0 + ((lane >> 3) & 1) * 8;
                uint32_t r[4];
                ldsm4(r, wb + (uint32_t)(nrow * LDS_H + kk) * 2);
                bf[2 * p][0] = r[0]; bf[2 * p][1] = r[1];
                bf[2 * p + 1][0] = r[2]; bf[2 * p + 1][1] = r[3];
            }
#pragma unroll
            for (int mf = 0; mf < 2; mf++)
#pragma unroll
                for (int nf = 0; nf < 8; nf++)
                    mma16816(acc[mf][nf], af[mf], bf[nf]);
        }
    };

    // ---- nt 0..3 : Q|K ----
    for (int nt = 0; nt < 4; nt++) {
        loadW((nt + 1) & 1, nt + 1);    // nt=3 prefetches nt=4 (V) into buf0
        cp_wait1();
        __syncthreads();
        const uint32_t wb = sb + PJ_W + (uint32_t)(nt & 1) * PJ_WSZ;
#pragma unroll
        for (int mh = 0; mh < 2; mh++) {
            compute(wb, mh);
#pragma unroll
            for (int mf = 0; mf < 2; mf++) {
#pragma unroll
                for (int nf = 0; nf < 8; nf++) {
                    int m = wm + mh * 32 + mf * 16 + (lane >> 2);
                    int n = nt * 256 + wn + nf * 8 + (lane & 3) * 2;
                    float b0 = g_bqkv[n], b1 = g_bqkv[n + 1];
                    *(__half2*)(Oqk + (size_t)m * NQK + n) =
                        __floats2half2_rn(acc[mf][nf][0] + b0, acc[mf][nf][1] + b1);
                    *(__half2*)(Oqk + (size_t)(m + 8) * NQK + n) =
                        __floats2half2_rn(acc[mf][nf][2] + b0, acc[mf][nf][3] + b1);
                }
            }
        }
        __syncthreads();
    }

    // ---- nt 4..5 : V, transpose-staged through the idle W buffer ----
    for (int vt = 0; vt < 2; vt++) {
        const uint32_t wcomp = sb + PJ_W;            // V weights always in buf0
        if (vt == 0) cp_wait0();
        __syncthreads();
        __half* st = (__half*)(smc + PJ_W + PJ_WSZ);
#pragma unroll
        for (int mh = 0; mh < 2; mh++) {
            compute(wcomp, mh);
#pragma unroll
            for (int mf = 0; mf < 2; mf++) {
#pragma unroll
                for (int nf = 0; nf < 8; nf++) {
                    int m = wm + mh * 32 + mf * 16 + (lane >> 2);
                    int n = wn + nf * 8 + (lane & 3) * 2;
                    float b0 = g_bqkv[1024 + vt * 256 + n];
                    float b1 = g_bqkv[1024 + vt * 256 + n + 1];
                    st[(size_t)n * LDS_H + m]           = __float2half(acc[mf][nf][0] + b0);
                    st[(size_t)(n + 1) * LDS_H + m]     = __float2half(acc[mf][nf][1] + b1);
                    st[(size_t)n * LDS_H + m + 8]       = __float2half(acc[mf][nf][2] + b0);
                    st[(size_t)(n + 1) * LDS_H + m + 8] = __float2half(acc[mf][nf][3] + b1);
                }
            }
        }
        __syncthreads();
        if (vt == 0) loadW(0, 5);                    // overlap W5 load with copy-out
        __half* Vout = g_vh + ((size_t)b * NCH + (size_t)vt * 256) * NP + p0;
#pragma unroll
        for (int i = 0; i < 16; i++) {
            int idx = i * 256 + tid, row = idx >> 4, col = (idx & 15) * 8;
            uint4 v = *(uint4*)(smc + PJ_W + PJ_WSZ + (uint32_t)(row * LDS_H + col) * 2);
            *(uint4*)(Vout + (size_t)row * NP + col) = v;
        }
        if (vt == 0) { cp_wait0(); }
        __syncthreads();
    }
}

// ---------------- fused flash attention v2 (R15 measured-best): m32 warps ------
// 8 warps x 32 query rows (CTA i-tile 256). S computed in n-quarters of 32
// (sacc transient 32 regs), exp'd + packed into persistent P regs; O fp32.
constexpr int FQ_ROWS = 256;
constexpr int FQ_BYTES = FQ_ROWS * LDS_H * 2;          // 69632
constexpr int FKV0     = FQ_BYTES;                     // 2 x (K,V) buffers
constexpr int FSMEM    = FKV0 + 4 * TILE_BYTES2;       // 208896 B

__global__ __launch_bounds__(256, 1) void flash_k() {
    extern __shared__ __half fsm[];
    const uint32_t sb = smem_u32(fsm);
    const int tid = threadIdx.x, lane = tid & 31, wid = tid >> 5;
    const int i0 = blockIdx.x * FQ_ROWS;
    const int z  = blockIdx.y;
    const int b  = z >> 2, h = z & 3;

    const __half* Qg = g_qkh + ((size_t)b * NP + i0) * NQK + h * 128;
    const __half* Kg = g_qkh + (size_t)b * NP * NQK + 512 + h * 128;
    const __half* Vg = g_vh  + (size_t)b * NCH * NP + (size_t)h * 128 * NP;

    // Q tile (256 rows) -> smem, joins group 0 with first KV load
#pragma unroll
    for (int i = 0; i < 16; i++) {
        int idx = i * 256 + tid, row = idx >> 4, col = (idx & 15) * 8;
        cp16(sb + (uint32_t)(row * LDS_H + col) * 2, Qg + (size_t)row * NQK + col);
    }
    auto loadKV = [&](int buf, int j0) {
        uint32_t kb = sb + FKV0 + (uint32_t)buf * 2 * TILE_BYTES2;
        uint32_t vb = kb + TILE_BYTES2;
#pragma unroll
        for (int i = 0; i < 8; i++) {
            int idx = i * 256 + tid, row = idx >> 4, col = (idx & 15) * 8;
            cp16(kb + (uint32_t)(row * LDS_H + col) * 2, Kg + (size_t)(j0 + row) * NQK + col);
            cp16(vb + (uint32_t)(row * LDS_H + col) * 2, Vg + (size_t)row * NP + j0 + col);
        }
        cp_commit();
    };
    loadKV(0, 0);

    const int wm = wid * 32;            // warp's 32 query rows
    uint32_t Pf[2][8][4];               // packed P: [mf][jstep][frag]
    float oacc[2][16][4] = {};          // [mf][ch-frag][quad]
    float l00 = 0.f, l01 = 0.f, l10 = 0.f, l11 = 0.f;   // l[mf][rowpair]

    for (int kc = 0; kc < 16; kc++) {
        if (kc + 1 < 16) { loadKV((kc + 1) & 1, (kc + 1) * 128); cp_wait1(); }
        else             { cp_wait0(); }
        __syncthreads();
        const uint32_t kb = sb + FKV0 + (uint32_t)(kc & 1) * 2 * TILE_BYTES2;
        const uint32_t vb = kb + TILE_BYTES2;

        // ---- S phase in n-quarters of 32; exp+pack into Pf ----
#pragma unroll
        for (int nq = 0; nq < 4; nq++) {
            float sq[2][4][4];
#pragma unroll
            for (int mf = 0; mf < 2; mf++)
#pragma unroll
                for (int nf = 0; nf < 4; nf++)
#pragma unroll
                    for (int q = 0; q < 4; q++) sq[mf][nf][q] = 0.f;
#pragma unroll
            for (int ks = 0; ks < 8; ks++) {
                const int k0 = ks * 16;
                uint32_t af[2][4];
#pragma unroll
                for (int mf = 0; mf < 2; mf++) {
                    int m  = wm + mf * 16 + (lane & 15);
                    int kk = k0 + (lane >> 4) * 8;
                    ldsm4(af[mf], sb + (uint32_t)(m * LDS_H + kk) * 2);
                }
                uint32_t bf[4][2];
#pragma unroll
                for (int p = 0; p < 2; p++) {
                    int nrow = nq * 32 + p * 16 + ((lane >> 4) & 1) * 8 + (lane & 7);
                    int kk   = k0 + ((lane >> 3) & 1) * 8;
                    uint32_t r[4];
                    ldsm4(r, kb + (uint32_t)(nrow * LDS_H + kk) * 2);
                    bf[2 * p][0] = r[0]; bf[2 * p][1] = r[1];
                    bf[2 * p + 1][0] = r[2]; bf[2 * p + 1][1] = r[3];
                }
#pragma unroll
                for (int mf = 0; mf < 2; mf++)
#pragma unroll
                    for (int nf = 0; nf < 4; nf++)
                        mma16816(sq[mf][nf], af[mf], bf[nf]);
            }
            // exp + l + pack (jsteps 2*nq, 2*nq+1)
#pragma unroll
            for (int mf = 0; mf < 2; mf++) {
#pragma unroll
                for (int lj = 0; lj < 2; lj++) {
                    float p0 = ex2(sq[mf][2 * lj][0]),     p1 = ex2(sq[mf][2 * lj][1]);
                    float p2 = ex2(sq[mf][2 * lj][2]),     p3 = ex2(sq[mf][2 * lj][3]);
                    float p4 = ex2(sq[mf][2 * lj + 1][0]), p5 = ex2(sq[mf][2 * lj + 1][1]);
                    float p6 = ex2(sq[mf][2 * lj + 1][2]), p7 = ex2(sq[mf][2 * lj + 1][3]);
                    if (mf == 0) { l00 += p0 + p1 + p4 + p5; l01 += p2 + p3 + p6 + p7; }
                    else         { l10 += p0 + p1 + p4 + p5; l11 += p2 + p3 + p6 + p7; }
                    __half2 h01 = __floats2half2_rn(p0, p1);
                    __half2 h23 = __floats2half2_rn(p2, p3);
                    __half2 h45 = __floats2half2_rn(p4, p5);
                    __half2 h67 = __floats2half2_rn(p6, p7);
                    Pf[mf][2 * nq + lj][0] = *(uint32_t*)&h01;
                    Pf[mf][2 * nq + lj][1] = *(uint32_t*)&h23;
                    Pf[mf][2 * nq + lj][2] = *(uint32_t*)&h45;
                    Pf[mf][2 * nq + lj][3] = *(uint32_t*)&h67;
                }
            }
        }

        // ---- O phase: oacc += P * V^T ----
#pragma unroll
        for (int js = 0; js < 8; js++) {
            uint32_t bfv[16][2];
#pragma unroll
            for (int p = 0; p < 8; p++) {
                int nrow = p * 16 + ((lane >> 4) & 1) * 8 + (lane & 7);
                int kk   = js * 16 + ((lane >> 3) & 1) * 8;
                uint32_t r[4];
                ldsm4(r, vb + (uint32_t)(nrow * LDS_H + kk) * 2);
                bfv[2 * p][0] = r[0]; bfv[2 * p][1] = r[1];
                bfv[2 * p + 1][0] = r[2]; bfv[2 * p + 1][1] = r[3];
            }
#pragma unroll
            for (int mf = 0; mf < 2; mf++)
#pragma unroll
                for (int nf = 0; nf < 16; nf++)
                    mma16816(oacc[mf][nf], Pf[mf][js], bfv[nf]);
        }
        __syncthreads();   // done reading buffer before next prefetch overwrites
    }

    // ---- epilogue: quad-reduce l, normalize, write att ----
    l00 += __shfl_xor_sync(0xffffffffu, l00, 1);
    l00 += __shfl_xor_sync(0xffffffffu, l00, 2);
    l01 += __shfl_xor_sync(0xffffffffu, l01, 1);
    l01 += __shfl_xor_sync(0xffffffffu, l01, 2);
    l10 += __shfl_xor_sync(0xffffffffu, l10, 1);
    l10 += __shfl_xor_sync(0xffffffffu, l10, 2);
    l11 += __shfl_xor_sync(0xffffffffu, l11, 1);
    l11 += __shfl_xor_sync(0xffffffffu, l11, 2);
    float inv[2][2] = { {1.f / l00, 1.f / l01}, {1.f / l10, 1.f / l11} };
    __half* ob = g_ath + (size_t)b * NP * NCH;
#pragma unroll
    for (int mf = 0; mf < 2; mf++) {
        const int row0 = i0 + wm + mf * 16 + (lane >> 2);
#pragma unroll
        for (int nf = 0; nf < 16; nf++) {
            int col = h * 128 + nf * 8 + (lane & 3) * 2;
            *(__half2*)(ob + (size_t)row0 * NCH + col) =
                __floats2half2_rn(oacc[mf][nf][0] * inv[mf][0],
                                  oacc[mf][nf][1] * inv[mf][0]);
            *(__half2*)(ob + (size_t)(row0 + 8) * NCH + col) =
                __floats2half2_rn(oacc[mf][nf][2] * inv[mf][1],
                                  oacc[mf][nf][3] * inv[mf][1]);
        }
    }
}

// ---------------- batchnorm statistics ---------------------------------------
__global__ __launch_bounds__(256) void bn_stats_k(const float* __restrict__ in,
                                                  const float* __restrict__ gamma,
                                                  const float* __restrict__ beta) {
    const int c = blockIdx.x;
    const int t = threadIdx.x;
    float s = 0.f, ss = 0.f;
    for (int idx = t; idx < NB * NP; idx += 256) {
        int b = idx >> 11;
        int p = idx & (NP - 1);
        float v = in[(size_t)b * NC * NP + (size_t)c * NP + p];
        s += v; ss += v * v;
    }
    __shared__ float r1[256], r2[256];
    r1[t] = s; r2[t] = ss;
    __syncthreads();
    for (int off = 128; off > 0; off >>= 1) {
        if (t < off) { r1[t] += r1[t + off]; r2[t] += r2[t + off]; }
        __syncthreads();
    }
    if (t == 0) {
        const float invN = 1.f / (NB * NP);
        float mean = r1[0] * invN;
        float var  = r2[0] * invN - mean * mean;
        float rstd = rsqrtf(var + 1e-5f);
        float sc = gamma[c] * rstd;
        g_scale[c] = sc;
        g_shift[c] = beta[c] - mean * sc;
    }
}

// ---------------- normalize + transpose: [b][c][p] f32 -> [b][p][c] half -------
__global__ __launch_bounds__(256) void norm_t_k(const float* __restrict__ in) {
    const int b = blockIdx.z;
    const int c0 = blockIdx.y * 32, p0 = blockIdx.x * 32;
    const int tx = threadIdx.x & 31, ty = threadIdx.x >> 5;   // 32 x 8
    __shared__ float s[32][33];
#pragma unroll
    for (int j = 0; j < 4; j++) {
        int c = c0 + ty + j * 8;
        float v = in[((size_t)b * NC + c) * NP + p0 + tx];
        s[ty + j * 8][tx] = v * g_scale[c] + g_shift[c];
    }
    __syncthreads();
#pragma unroll
    for (int j = 0; j < 4; j++) {
        int p = p0 + ty + j * 8;
        g_xh[((size_t)b * NP + p) * NC + c0 + tx] = __float2half(s[tx][ty + j * 8]);
    }
}

// ---------------- weight prep --------------------------------------------------
__global__ __launch_bounds__(256) void wprep_k(
    const float* __restrict__ Wq, const float* __restrict__ bq,
    const float* __restrict__ Wk, const float* __restrict__ bk,
    const float* __restrict__ Wv, const float* __restrict__ bv,
    const float* __restrict__ Wo)
{
    const float CE = 0.08838834764831845f * 1.4426950408889634f;
    int idx = blockIdx.x * 256 + threadIdx.x;   // 0..262143
    if (idx < 196608) {
        int o = idx >> 7, c = idx & 127;
        int sect = o >> 9;              // 0=q 1=k 2=v
        int op = o & 511, h = op >> 7, cp = op & 127;
        const float* W = (sect == 0) ? Wq : (sect == 1) ? Wk : Wv;
        float scale = (sect == 0) ? CE : 1.f;
        g_wqkv[idx] = __float2half(W[(cp * 4 + h) * 128 + c] * scale);
    } else {
        int t = idx - 196608;
        int o2 = t >> 9, op = t & 511;
        int h = op >> 7, cp = op & 127;
        g_wo[t] = __float2half(Wo[o2 * 512 + cp * 4 + h]);
    }
    if (idx < 1536) {
        int sect = idx >> 9, op = idx & 511, h = op >> 7, cp = op & 127;
        const float* bb = (sect == 0) ? bq : (sect == 1) ? bk : bv;
        float scale = (sect == 0) ? CE : 1.f;
        g_bqkv[idx] = bb[cp * 4 + h] * scale;
    }
}

// ---------------- launch ------------------------------------------------------
extern "C" void kernel_launch(void* const* d_in, const int* in_sizes, int n_in,
                              void* d_out, int out_size) {
    const float* input = (const float*)d_in[0];
    const float* gamma = (const float*)d_in[1];
    const float* beta  = (const float*)d_in[2];
    const float* Wq    = (const float*)d_in[3];
    const float* bq    = (const float*)d_in[4];
    const float* Wk    = (const float*)d_in[5];
    const float* bk    = (const float*)d_in[6];
    const float* Wv    = (const float*)d_in[7];
    const float* bv    = (const float*)d_in[8];
    const float* Wo    = (const float*)d_in[9];
    const float* bo    = (const float*)d_in[10];
    float* out = (float*)d_out;

    __half *pwo, *path;
    cudaGetSymbolAddress((void**)&pwo,  g_wo);
    cudaGetSymbolAddress((void**)&path, g_ath);

    cudaFuncSetAttribute(hgemm_nt<float, 4>, cudaFuncAttributeMaxDynamicSharedMemorySize, 2 * BUF_BYTES);
    cudaFuncSetAttribute(proj_k,  cudaFuncAttributeMaxDynamicSharedMemorySize, PJ_SMEM);
    cudaFuncSetAttribute(flash_k, cudaFuncAttributeMaxDynamicSharedMemorySize, FSMEM);

    // 1) batchnorm stats, normalize+transpose, weight prep
    bn_stats_k<<<NC, 256>>>(input, gamma, beta);
    wprep_k<<<1024, 256>>>(Wq, bq, Wk, bk, Wv, bv, Wo);
    norm_t_k<<<dim3(NP / 32, NC / 32, NB), 256>>>(input);

    // 2) fused QKV projection -> qk[b][p][1024], v[b][(h,c')][p]
    proj_k<<<dim3(NP / 128, NB), 256, PJ_SMEM>>>();

    // 3) fused attention v2: 256-row i-tiles, m32 warps, S in n-quarters
    flash_k<<<dim3(NP / FQ_ROWS, NZ), 256, FSMEM>>>();

    // 4) out = Wo' att + bo + input : M=128 N=2048 K=512 per batch
    hgemm_nt<float, 4><<<dim3(16, 1, NB), 256, 2 * BUF_BYTES>>>(
        pwo, path, out, bo, input,
        4, NCH, NCH, NP,
        0, 0, (long)NP * NCH, 0, (long)NC * NP, 0, 1, 1.f);
}